// round 1
// baseline (speedup 1.0000x reference)
#include <cuda_runtime.h>

#define T_STEPS 512
#define BATCH   64
#define HID     512
#define NB_REC  128
#define NT_REC  128
#define HS_STRIDE 68   // padded row stride (floats) for transposed h tile in smem

// ---------------- scratch (static device allocations; no cudaMalloc) ----------------
__device__ float g_xg[(size_t)T_STEPS * BATCH * 3 * HID]; // 201 MB: precomputed input gates
__device__ float g_y0[(size_t)T_STEPS * BATCH * HID];     // 67 MB: layer-0 output
__device__ float g_h[2 * BATCH * HID];                    // ping-pong hidden state
__device__ unsigned g_bar_count = 0;
__device__ volatile unsigned g_bar_gen = 0;

// ---------------- packed fp32x2 FMA (Blackwell FFMA2) ----------------
__device__ __forceinline__ float2 ffma2(float2 a, float2 b, float2 c) {
    float2 d;
    asm("fma.rn.f32x2 %0, %1, %2, %3;"
        : "=l"(reinterpret_cast<unsigned long long&>(d))
        : "l"(reinterpret_cast<unsigned long long&>(a)),
          "l"(reinterpret_cast<unsigned long long&>(b)),
          "l"(reinterpret_cast<unsigned long long&>(c)));
    return d;
}

// ---------------- grid-wide barrier (all blocks resident: 1 block/SM, 128 <= 148) ----------------
__device__ __forceinline__ void grid_barrier(int nblocks) {
    __syncthreads();
    if (threadIdx.x == 0) {
        unsigned gen = g_bar_gen;
        __threadfence();
        unsigned ticket = atomicAdd(&g_bar_count, 1u);
        if (ticket == (unsigned)(nblocks - 1)) {
            g_bar_count = 0;
            __threadfence();
            g_bar_gen = gen + 1u;
        } else {
            while (g_bar_gen == gen) { __nanosleep(64); }
        }
        __threadfence();
    }
    __syncthreads();
}

// ---------------- GEMM: out[M,N] = A[M,K] * W[N,K]^T + bias, M=32768, N=1536 ----------------
// 128x128 tile, BK=16, 256 threads, 8x8 microtile with f32x2 FMAs.
__global__ void __launch_bounds__(256) gemm_bias_kernel(
    const float* __restrict__ A, const float* __restrict__ W,
    const float* __restrict__ bias, float* __restrict__ out, int K)
{
    __shared__ float As[16 * 132];
    __shared__ float Bs[16 * 132];

    const int tid = threadIdx.x;
    const int m0 = blockIdx.y * 128;
    const int n0 = blockIdx.x * 128;
    const int tm = tid >> 4;   // 0..15
    const int tn = tid & 15;   // 0..15

    float2 c2[8][4];
#pragma unroll
    for (int i = 0; i < 8; ++i)
#pragma unroll
        for (int p = 0; p < 4; ++p) c2[i][p] = make_float2(0.f, 0.f);

    for (int kt = 0; kt < K; kt += 16) {
#pragma unroll
        for (int u = 0; u < 2; ++u) {
            int s   = tid + u * 256;      // 0..511
            int row = s >> 2;             // 0..127
            int c4  = s & 3;              // 0..3
            float4 av = *(const float4*)(A + (size_t)(m0 + row) * K + kt + c4 * 4);
            As[(c4 * 4 + 0) * 132 + row] = av.x;
            As[(c4 * 4 + 1) * 132 + row] = av.y;
            As[(c4 * 4 + 2) * 132 + row] = av.z;
            As[(c4 * 4 + 3) * 132 + row] = av.w;
            float4 bv = *(const float4*)(W + (size_t)(n0 + row) * K + kt + c4 * 4);
            Bs[(c4 * 4 + 0) * 132 + row] = bv.x;
            Bs[(c4 * 4 + 1) * 132 + row] = bv.y;
            Bs[(c4 * 4 + 2) * 132 + row] = bv.z;
            Bs[(c4 * 4 + 3) * 132 + row] = bv.w;
        }
        __syncthreads();

#pragma unroll
        for (int kb = 0; kb < 16; ++kb) {
            float4 a0 = *(const float4*)(As + kb * 132 + tm * 8);
            float4 a1 = *(const float4*)(As + kb * 132 + tm * 8 + 4);
            float4 b0 = *(const float4*)(Bs + kb * 132 + tn * 8);
            float4 b1 = *(const float4*)(Bs + kb * 132 + tn * 8 + 4);
            float av[8] = {a0.x, a0.y, a0.z, a0.w, a1.x, a1.y, a1.z, a1.w};
            float2 bp[4] = {make_float2(b0.x, b0.y), make_float2(b0.z, b0.w),
                            make_float2(b1.x, b1.y), make_float2(b1.z, b1.w)};
#pragma unroll
            for (int i = 0; i < 8; ++i) {
                float2 as = make_float2(av[i], av[i]);
#pragma unroll
                for (int p = 0; p < 4; ++p) c2[i][p] = ffma2(as, bp[p], c2[i][p]);
            }
        }
        __syncthreads();
    }

    const float4 bb0 = *(const float4*)(bias + n0 + tn * 8);
    const float4 bb1 = *(const float4*)(bias + n0 + tn * 8 + 4);
#pragma unroll
    for (int i = 0; i < 8; ++i) {
        int m = m0 + tm * 8 + i;
        float4 o0 = make_float4(c2[i][0].x + bb0.x, c2[i][0].y + bb0.y,
                                c2[i][1].x + bb0.z, c2[i][1].y + bb0.w);
        float4 o1 = make_float4(c2[i][2].x + bb1.x, c2[i][2].y + bb1.y,
                                c2[i][3].x + bb1.z, c2[i][3].y + bb1.w);
        float* dst = out + (size_t)m * 1536 + n0 + tn * 8;
        *(float4*)(dst)     = o0;
        *(float4*)(dst + 4) = o1;
    }
}

// ---------------- persistent GRU recurrence ----------------
// 128 blocks x 128 threads. Block b owns 4 h-columns j0=4*bid (W rows j, H+j, 2H+j).
// thread = (kk: k-half, rg: which of 4 columns, bg: batch group of 4)
__global__ void __launch_bounds__(NT_REC, 1) gru_rec_kernel(
    const float* __restrict__ xg, const float* __restrict__ Whh,
    const float* __restrict__ bhh, float* __restrict__ y,
    float* __restrict__ hn_out, float* __restrict__ hbuf)
{
    extern __shared__ float smem[];
    float* Ws  = smem;                      // 12 * 512
    float* hs  = Ws + 12 * HID;             // 512 * 68  (k-major, padded)
    float* red = hs + HID * HS_STRIDE;      // 64 * 12

    const int tid = threadIdx.x;
    const int j0  = blockIdx.x * 4;
    const int kk  = tid >> 6;        // 0..1
    const int rem = tid & 63;
    const int rg  = rem >> 4;        // 0..3
    const int bg  = rem & 15;        // 0..15

    // preload W slice (12 rows x 512), invariant across all time steps
    for (int idx = tid; idx < 12 * HID; idx += NT_REC) {
        int lr = idx >> 9;          // local row 0..11
        int k  = idx & 511;
        int g  = lr >> 2;           // gate
        int jj = lr & 3;            // column within block
        Ws[idx] = Whh[(size_t)(g * HID + j0 + jj) * HID + k];
    }

    const int j = j0 + rg;
    float bhr = 0.f, bhz = 0.f, bhn = 0.f;
    if (kk == 0) { bhr = bhh[j]; bhz = bhh[HID + j]; bhn = bhh[2 * HID + j]; }

    const int sb = tid & 63;   // staging: batch
    const int sh = tid >> 6;   // staging: k half

    for (int t = 0; t < T_STEPS; ++t) {
        const float* hcur  = hbuf + (t & 1) * BATCH * HID;
        float*       hnext = hbuf + ((t + 1) & 1) * BATCH * HID;

        // stage h (global [b][k]) -> hs transposed ([k][b], stride 68). t==0: zeros.
        if (t == 0) {
            for (int q = 0; q < 64; ++q) {
                int k = sh * 256 + q * 4;
                hs[(k + 0) * HS_STRIDE + sb] = 0.f;
                hs[(k + 1) * HS_STRIDE + sb] = 0.f;
                hs[(k + 2) * HS_STRIDE + sb] = 0.f;
                hs[(k + 3) * HS_STRIDE + sb] = 0.f;
            }
        } else {
            const float4* src = (const float4*)(hcur + sb * HID + sh * 256);
#pragma unroll 4
            for (int q = 0; q < 64; ++q) {
                float4 v = src[q];
                int k = sh * 256 + q * 4;
                hs[(k + 0) * HS_STRIDE + sb] = v.x;
                hs[(k + 1) * HS_STRIDE + sb] = v.y;
                hs[(k + 2) * HS_STRIDE + sb] = v.z;
                hs[(k + 3) * HS_STRIDE + sb] = v.w;
            }
        }
        __syncthreads();

        // partial dots over this thread's k-half for (4 batches) x (3 gates) of column j
        float2 ar0 = {0,0}, ar1 = {0,0}, az0 = {0,0}, az1 = {0,0}, an0 = {0,0}, an1 = {0,0};
        const float* wr = Ws + (0 * 4 + rg) * HID;
        const float* wz = Ws + (1 * 4 + rg) * HID;
        const float* wn = Ws + (2 * 4 + rg) * HID;
        const int kbase = kk * 256;
#pragma unroll 2
        for (int k4 = 0; k4 < 256; k4 += 4) {
            const int k = kbase + k4;
            float4 w4r = *(const float4*)(wr + k);
            float4 w4z = *(const float4*)(wz + k);
            float4 w4n = *(const float4*)(wn + k);
            float wra[4] = {w4r.x, w4r.y, w4r.z, w4r.w};
            float wza[4] = {w4z.x, w4z.y, w4z.z, w4z.w};
            float wna[4] = {w4n.x, w4n.y, w4n.z, w4n.w};
#pragma unroll
            for (int c = 0; c < 4; ++c) {
                float4 hv = *(const float4*)(hs + (k + c) * HS_STRIDE + bg * 4);
                float2 h01 = make_float2(hv.x, hv.y);
                float2 h23 = make_float2(hv.z, hv.w);
                float2 ws;
                ws = make_float2(wra[c], wra[c]);
                ar0 = ffma2(ws, h01, ar0);  ar1 = ffma2(ws, h23, ar1);
                ws = make_float2(wza[c], wza[c]);
                az0 = ffma2(ws, h01, az0);  az1 = ffma2(ws, h23, az1);
                ws = make_float2(wna[c], wna[c]);
                an0 = ffma2(ws, h01, an0);  an1 = ffma2(ws, h23, an1);
            }
        }

        // cross-k-half reduction + gates + state update (kk==0 lanes finalize)
        if (kk == 1) {
            float2* r2 = (float2*)red + (rg * 16 + bg) * 6;
            r2[0] = ar0; r2[1] = ar1; r2[2] = az0; r2[3] = az1; r2[4] = an0; r2[5] = an1;
        }
        __syncthreads();
        if (kk == 0) {
            const float2* r2 = (const float2*)red + (rg * 16 + bg) * 6;
            ar0.x += r2[0].x; ar0.y += r2[0].y; ar1.x += r2[1].x; ar1.y += r2[1].y;
            az0.x += r2[2].x; az0.y += r2[2].y; az1.x += r2[3].x; az1.y += r2[3].y;
            an0.x += r2[4].x; an0.y += r2[4].y; an1.x += r2[5].x; an1.y += r2[5].y;

            float hrv[4] = {ar0.x + bhr, ar0.y + bhr, ar1.x + bhr, ar1.y + bhr};
            float hzv[4] = {az0.x + bhz, az0.y + bhz, az1.x + bhz, az1.y + bhz};
            float hnv[4] = {an0.x + bhn, an0.y + bhn, an1.x + bhn, an1.y + bhn};

            const float* xgt = xg + (size_t)t * BATCH * 3 * HID + j;
#pragma unroll
            for (int i = 0; i < 4; ++i) {
                int b = bg * 4 + i;
                const float* xp = xgt + (size_t)b * 3 * HID;
                float xrv = xp[0];
                float xzv = xp[HID];
                float xnv = xp[2 * HID];
                float r = 1.f / (1.f + __expf(-(xrv + hrv[i])));
                float z = 1.f / (1.f + __expf(-(xzv + hzv[i])));
                float n = tanhf(xnv + r * hnv[i]);
                float hold = hs[j * HS_STRIDE + b];
                float hv = (1.f - z) * n + z * hold;
                hnext[b * HID + j] = hv;
                y[((size_t)t * BATCH + b) * HID + j] = hv;
                if (t == T_STEPS - 1) hn_out[b * HID + j] = hv;
            }
        }
        grid_barrier(NB_REC);
    }
}

// ---------------- launch ----------------
extern "C" void kernel_launch(void* const* d_in, const int* in_sizes, int n_in,
                              void* d_out, int out_size) {
    const float* x    = (const float*)d_in[0];
    const float* Wih0 = (const float*)d_in[1];
    const float* Whh0 = (const float*)d_in[2];
    const float* bih0 = (const float*)d_in[3];
    const float* bhh0 = (const float*)d_in[4];
    const float* Wih1 = (const float*)d_in[5];
    const float* Whh1 = (const float*)d_in[6];
    const float* bih1 = (const float*)d_in[7];
    const float* bhh1 = (const float*)d_in[8];

    float* out = (float*)d_out;
    float* y1  = out;
    float* hn0 = out + (size_t)T_STEPS * BATCH * HID;  // hn[0]
    float* hn1 = hn0 + BATCH * HID;                    // hn[1]

    float *xg, *y0, *hb;
    cudaGetSymbolAddress((void**)&xg, g_xg);
    cudaGetSymbolAddress((void**)&y0, g_y0);
    cudaGetSymbolAddress((void**)&hb, g_h);

    const int rec_smem = (12 * HID + HID * HS_STRIDE + 64 * 12) * 4; // 166912 B
    cudaFuncSetAttribute(gru_rec_kernel, cudaFuncAttributeMaxDynamicSharedMemorySize, rec_smem);

    dim3 ggrid(12, 256);  // N/128 = 12, M/128 = 256

    // layer 0
    gemm_bias_kernel<<<ggrid, 256>>>(x, Wih0, bih0, xg, 256);
    gru_rec_kernel<<<NB_REC, NT_REC, rec_smem>>>(xg, Whh0, bhh0, y0, hn0, hb);
    // layer 1
    gemm_bias_kernel<<<ggrid, 256>>>(y0, Wih1, bih1, xg, 512);
    gru_rec_kernel<<<NB_REC, NT_REC, rec_smem>>>(xg, Whh1, bhh1, y1, hn1, hb);
}

// round 2
// speedup vs baseline: 1.9552x; 1.9552x over previous
#include <cuda_runtime.h>

#define T_STEPS 512
#define BATCH   64
#define HID     512
#define GATES3  1536
#define NB_REC  128
#define NT_REC  128
#define WROW    514   // float2 stride for W rows (padded)
#define HROW    516   // float stride for h rows (padded)

// ---------------- scratch (static device allocations; no cudaMalloc) ----------------
__device__ float g_xg[(size_t)T_STEPS * BATCH * GATES3]; // precomputed input gates
__device__ float g_y0[(size_t)T_STEPS * BATCH * HID];    // layer-0 output
__device__ float g_hx[2 * BATCH * HID];                  // ping-pong h exchange [parity][b][j]
__device__ unsigned g_flags[NB_REC];                     // per-block step flags (reset each launch)
__device__ unsigned g_end_cnt[8];
__device__ volatile unsigned g_end_gen[8];

// ---------------- packed fp32x2 FMA (Blackwell FFMA2) ----------------
__device__ __forceinline__ float2 ffma2(float2 a, float2 b, float2 c) {
    float2 d;
    asm("fma.rn.f32x2 %0, %1, %2, %3;"
        : "=l"(reinterpret_cast<unsigned long long&>(d))
        : "l"(reinterpret_cast<unsigned long long&>(a)),
          "l"(reinterpret_cast<unsigned long long&>(b)),
          "l"(reinterpret_cast<unsigned long long&>(c)));
    return d;
}

__device__ __forceinline__ float sigmoidf_(float x) {
    return 1.f / (1.f + __expf(-x));
}

// ---------------- GEMM: out[M,N] = A[M,K] * W[N,K]^T + bias ----------------
__global__ void __launch_bounds__(256) gemm_bias_kernel(
    const float* __restrict__ A, const float* __restrict__ W,
    const float* __restrict__ bias, float* __restrict__ out, int K)
{
    __shared__ float As[16 * 132];
    __shared__ float Bs[16 * 132];

    const int tid = threadIdx.x;
    const int m0 = blockIdx.y * 128;
    const int n0 = blockIdx.x * 128;
    const int tm = tid >> 4;
    const int tn = tid & 15;

    float2 c2[8][4];
#pragma unroll
    for (int i = 0; i < 8; ++i)
#pragma unroll
        for (int p = 0; p < 4; ++p) c2[i][p] = make_float2(0.f, 0.f);

    for (int kt = 0; kt < K; kt += 16) {
#pragma unroll
        for (int u = 0; u < 2; ++u) {
            int s   = tid + u * 256;
            int row = s >> 2;
            int c4  = s & 3;
            float4 av = *(const float4*)(A + (size_t)(m0 + row) * K + kt + c4 * 4);
            As[(c4 * 4 + 0) * 132 + row] = av.x;
            As[(c4 * 4 + 1) * 132 + row] = av.y;
            As[(c4 * 4 + 2) * 132 + row] = av.z;
            As[(c4 * 4 + 3) * 132 + row] = av.w;
            float4 bv = *(const float4*)(W + (size_t)(n0 + row) * K + kt + c4 * 4);
            Bs[(c4 * 4 + 0) * 132 + row] = bv.x;
            Bs[(c4 * 4 + 1) * 132 + row] = bv.y;
            Bs[(c4 * 4 + 2) * 132 + row] = bv.z;
            Bs[(c4 * 4 + 3) * 132 + row] = bv.w;
        }
        __syncthreads();

#pragma unroll
        for (int kb = 0; kb < 16; ++kb) {
            float4 a0 = *(const float4*)(As + kb * 132 + tm * 8);
            float4 a1 = *(const float4*)(As + kb * 132 + tm * 8 + 4);
            float4 b0 = *(const float4*)(Bs + kb * 132 + tn * 8);
            float4 b1 = *(const float4*)(Bs + kb * 132 + tn * 8 + 4);
            float av[8] = {a0.x, a0.y, a0.z, a0.w, a1.x, a1.y, a1.z, a1.w};
            float2 bp[4] = {make_float2(b0.x, b0.y), make_float2(b0.z, b0.w),
                            make_float2(b1.x, b1.y), make_float2(b1.z, b1.w)};
#pragma unroll
            for (int i = 0; i < 8; ++i) {
                float2 as = make_float2(av[i], av[i]);
#pragma unroll
                for (int p = 0; p < 4; ++p) c2[i][p] = ffma2(as, bp[p], c2[i][p]);
            }
        }
        __syncthreads();
    }

    const float4 bb0 = *(const float4*)(bias + n0 + tn * 8);
    const float4 bb1 = *(const float4*)(bias + n0 + tn * 8 + 4);
#pragma unroll
    for (int i = 0; i < 8; ++i) {
        int m = m0 + tm * 8 + i;
        float4 o0 = make_float4(c2[i][0].x + bb0.x, c2[i][0].y + bb0.y,
                                c2[i][1].x + bb0.z, c2[i][1].y + bb0.w);
        float4 o1 = make_float4(c2[i][2].x + bb1.x, c2[i][2].y + bb1.y,
                                c2[i][3].x + bb1.z, c2[i][3].y + bb1.w);
        float* dst = out + (size_t)m * GATES3 + n0 + tn * 8;
        *(float4*)(dst)     = o0;
        *(float4*)(dst + 4) = o1;
    }
}

// ---------------- persistent GRU recurrence (grouped: 16 col-groups x 8 batch-groups) ----
// Block (cg, grp): owns columns j0=cg*32..+32, batches b0=grp*8..+8.
// Thread (cp, bsub): 2 columns (j0+2cp, +1), 1 batch (b0+bsub), full k=512 dot.
// Only 16 KB of h exchanged per step within each 16-block group; no global barrier.
__global__ void __launch_bounds__(NT_REC, 1) gru_rec_kernel(
    const float* __restrict__ xg, const float* __restrict__ Whh,
    const float* __restrict__ bhh, float* __restrict__ y,
    float* __restrict__ hn_out)
{
    extern __shared__ float smem[];
    float2* Ws2 = (float2*)smem;                 // 48 rows x 514 float2 (col-pairs interleaved)
    float*  hs  = smem + 48 * WROW * 2;          // 8 rows x 516 floats

    const int tid  = threadIdx.x;
    const int bid  = blockIdx.x;
    const int cg   = bid & 15;
    const int grp  = bid >> 4;
    const int j0   = cg * 32;
    const int b0   = grp * 8;
    const int cp   = tid >> 3;   // 0..15 col-pair
    const int bsub = tid & 7;    // 0..7 batch
    const int b    = b0 + bsub;
    const int jj   = j0 + cp * 2;

    // one-time: load W_hh slice, interleaving column pairs: Ws2[g*16+cp][k] = (W[j][k], W[j+1][k])
    for (int idx = tid; idx < 48 * 512; idx += NT_REC) {
        int row = idx >> 9;
        int k   = idx & 511;
        int g   = row >> 4;
        int cpp = row & 15;
        int col = j0 + cpp * 2;
        Ws2[row * WROW + k] = make_float2(
            Whh[(size_t)(g * HID + col) * HID + k],
            Whh[(size_t)(g * HID + col + 1) * HID + k]);
    }
    for (int idx = tid; idx < 8 * HROW; idx += NT_REC) hs[idx] = 0.f;

    const float2 bhr = *(const float2*)(bhh + jj);
    const float2 bhz = *(const float2*)(bhh + HID + jj);
    const float2 bhn = *(const float2*)(bhh + 2 * HID + jj);

    const float2* wr = Ws2 + cp * WROW;
    const float2* wz = Ws2 + (16 + cp) * WROW;
    const float2* wn = Ws2 + (32 + cp) * WROW;
    const float*  hb = hs + bsub * HROW;

    const size_t xofs = (size_t)b * GATES3 + jj;
    float2 xr = *(const float2*)(xg + xofs);
    float2 xz = *(const float2*)(xg + xofs + HID);
    float2 xn = *(const float2*)(xg + xofs + 2 * HID);

    float2 hp = make_float2(0.f, 0.f);   // this thread's own h (hold path in regs)
    __syncthreads();

    for (int t = 0; t < T_STEPS; ++t) {
        if (t > 0) {
            // group barrier: wait until all 16 blocks of this group posted step t-1
            if (tid < 16) {
                const unsigned* fp = &g_flags[grp * 16 + tid];
                unsigned v;
                do {
                    asm volatile("ld.acquire.gpu.global.u32 %0, [%1];" : "=r"(v) : "l"(fp));
                } while (v < (unsigned)t);
            }
            __syncthreads();
            // stage 16 KB: h of this group's 8 batches (L2-only loads; L1 never caches g_hx)
            const float* hsrc = g_hx + (size_t)(t & 1) * BATCH * HID;
#pragma unroll
            for (int i = 0; i < 8; ++i) {
                int idx = tid + i * 128;
                int bb  = idx >> 7;
                int kq  = idx & 127;
                float4 v = __ldcg((const float4*)(hsrc + (size_t)(b0 + bb) * HID + kq * 4));
                *(float4*)(hs + bb * HROW + kq * 4) = v;
            }
            __syncthreads();
        }

        // prefetch next step's xg (independent of h; lands during the FMA loop)
        float2 nxr = make_float2(0.f, 0.f), nxz = nxr, nxn = nxr;
        if (t + 1 < T_STEPS) {
            const float* xp = xg + (size_t)(t + 1) * BATCH * GATES3 + xofs;
            nxr = *(const float2*)(xp);
            nxz = *(const float2*)(xp + HID);
            nxn = *(const float2*)(xp + 2 * HID);
        }

        // full-k dot for 2 columns x 3 gates x 1 batch; FFMA2 packs the column pair
        float2 ar = {0, 0}, az = {0, 0}, an = {0, 0};
        float2 ar2 = {0, 0}, az2 = {0, 0}, an2 = {0, 0};
#pragma unroll 4
        for (int k = 0; k < HID; k += 4) {
            float4 hv  = *(const float4*)(hb + k);
            float4 r01 = *(const float4*)(wr + k);
            float4 r23 = *(const float4*)(wr + k + 2);
            float4 z01 = *(const float4*)(wz + k);
            float4 z23 = *(const float4*)(wz + k + 2);
            float4 n01 = *(const float4*)(wn + k);
            float4 n23 = *(const float4*)(wn + k + 2);
            ar  = ffma2(make_float2(r01.x, r01.y), make_float2(hv.x, hv.x), ar);
            az  = ffma2(make_float2(z01.x, z01.y), make_float2(hv.x, hv.x), az);
            an  = ffma2(make_float2(n01.x, n01.y), make_float2(hv.x, hv.x), an);
            ar2 = ffma2(make_float2(r01.z, r01.w), make_float2(hv.y, hv.y), ar2);
            az2 = ffma2(make_float2(z01.z, z01.w), make_float2(hv.y, hv.y), az2);
            an2 = ffma2(make_float2(n01.z, n01.w), make_float2(hv.y, hv.y), an2);
            ar  = ffma2(make_float2(r23.x, r23.y), make_float2(hv.z, hv.z), ar);
            az  = ffma2(make_float2(z23.x, z23.y), make_float2(hv.z, hv.z), az);
            an  = ffma2(make_float2(n23.x, n23.y), make_float2(hv.z, hv.z), an);
            ar2 = ffma2(make_float2(r23.z, r23.w), make_float2(hv.w, hv.w), ar2);
            az2 = ffma2(make_float2(z23.z, z23.w), make_float2(hv.w, hv.w), az2);
            an2 = ffma2(make_float2(n23.z, n23.w), make_float2(hv.w, hv.w), an2);
        }

        float hrx = ar.x + ar2.x + bhr.x, hry = ar.y + ar2.y + bhr.y;
        float hzx = az.x + az2.x + bhz.x, hzy = az.y + az2.y + bhz.y;
        float hnx = an.x + an2.x + bhn.x, hny = an.y + an2.y + bhn.y;

        float rX = sigmoidf_(xr.x + hrx), rY = sigmoidf_(xr.y + hry);
        float zX = sigmoidf_(xz.x + hzx), zY = sigmoidf_(xz.y + hzy);
        float nX = tanhf(xn.x + rX * hnx), nY = tanhf(xn.y + rY * hny);
        float hX = (1.f - zX) * nX + zX * hp.x;
        float hY = (1.f - zY) * nY + zY * hp.y;
        hp = make_float2(hX, hY);

        // publish h slice + outputs
        float* hdst = g_hx + (size_t)((t + 1) & 1) * BATCH * HID + (size_t)b * HID + jj;
        *(float2*)hdst = hp;
        *(float2*)(y + ((size_t)t * BATCH + b) * HID + jj) = hp;
        if (t == T_STEPS - 1) *(float2*)(hn_out + (size_t)b * HID + jj) = hp;

        __syncthreads();
        if (tid == 0 && t < T_STEPS - 1) {
            __threadfence();
            asm volatile("st.global.cg.u32 [%0], %1;"
                         :: "l"(&g_flags[bid]), "r"((unsigned)(t + 1)) : "memory");
        }
        xr = nxr; xz = nxz; xn = nxn;
    }

    // end-of-launch: group gen-barrier (replay-safe), then reset own flag for next launch
    __syncthreads();
    if (tid == 0) {
        unsigned gen = g_end_gen[grp];
        __threadfence();
        if (atomicAdd(&g_end_cnt[grp], 1u) == 15u) {
            g_end_cnt[grp] = 0u;
            __threadfence();
            g_end_gen[grp] = gen + 1u;
        } else {
            while (g_end_gen[grp] == gen) { __nanosleep(32); }
        }
        g_flags[bid] = 0u;
        __threadfence();
    }
}

// ---------------- launch ----------------
extern "C" void kernel_launch(void* const* d_in, const int* in_sizes, int n_in,
                              void* d_out, int out_size) {
    const float* x    = (const float*)d_in[0];
    const float* Wih0 = (const float*)d_in[1];
    const float* Whh0 = (const float*)d_in[2];
    const float* bih0 = (const float*)d_in[3];
    const float* bhh0 = (const float*)d_in[4];
    const float* Wih1 = (const float*)d_in[5];
    const float* Whh1 = (const float*)d_in[6];
    const float* bih1 = (const float*)d_in[7];
    const float* bhh1 = (const float*)d_in[8];

    float* out = (float*)d_out;
    float* y1  = out;
    float* hn0 = out + (size_t)T_STEPS * BATCH * HID;
    float* hn1 = hn0 + BATCH * HID;

    float *xg, *y0;
    cudaGetSymbolAddress((void**)&xg, g_xg);
    cudaGetSymbolAddress((void**)&y0, g_y0);

    const int rec_smem = (48 * WROW * 2 + 8 * HROW) * 4;  // 213,888 B
    cudaFuncSetAttribute(gru_rec_kernel, cudaFuncAttributeMaxDynamicSharedMemorySize, rec_smem);

    dim3 ggrid(12, 256);

    gemm_bias_kernel<<<ggrid, 256>>>(x, Wih0, bih0, xg, 256);
    gru_rec_kernel<<<NB_REC, NT_REC, rec_smem>>>(xg, Whh0, bhh0, y0, hn0);
    gemm_bias_kernel<<<ggrid, 256>>>(y0, Wih1, bih1, xg, 512);
    gru_rec_kernel<<<NB_REC, NT_REC, rec_smem>>>(xg, Whh1, bhh1, y1, hn1);
}